// round 1
// baseline (speedup 1.0000x reference)
#include <cuda_runtime.h>
#include <math.h>
#include <stdint.h>

#define N_PTS 65536
#define DIMS  64
#define KCL   128
#define CHUNK 256
#define NBLK  (N_PTS / CHUNK)   // 256
#define KD    (KCL * DIMS)      // 8192
#define EPSV  1e-8f
#define BIGF  3.402823466e38f

// ----------------------------------------------------------------------------
// Device scratch (static, no allocation)
// ----------------------------------------------------------------------------
__device__ int    g_pred[N_PTS];
__device__ int    g_histx[NBLK * KCL];
__device__ int    g_histt[NBLK * KCL];
__device__ float  g_fill[KCL];
__device__ int    g_m[KCL];
__device__ int    g_P[KCL];
__device__ int    g_off[KCL];
__device__ double g_loss[2];   // [0] = loss_fil, [1] = loss_med
// Padded gathered buffers: sum of per-cluster pow2 sizes <= 2*N rows, 64 feats
__device__ float  g_xg[(size_t)(2 * N_PTS) * DIMS];
__device__ float  g_tg[(size_t)(2 * N_PTS) * DIMS];

// ----------------------------------------------------------------------------
// K0: zero accumulators
// ----------------------------------------------------------------------------
__global__ void k_init() {
    int t = threadIdx.x;
    if (t < KCL) g_fill[t] = 0.0f;
    if (t < 2)   g_loss[t] = 0.0;
}

// ----------------------------------------------------------------------------
// K1: per-point distances to all 128 centers, argmin (pred), soft filling,
//     per-block cluster histogram of x-assignments.
//     d2 = |x|^2 + |c|^2 - 2 x.c  (same form as reference), dist = sqrt(max(d2,0))
// ----------------------------------------------------------------------------
__global__ void k_assign(const float* __restrict__ x, const float* __restrict__ cc) {
    __shared__ float sc[KCL * DIMS];   // centers, 32 KB
    __shared__ float scn[KCL];         // |c|^2
    __shared__ float sfill[KCL];
    __shared__ int   shist[KCL];
    const int tid = threadIdx.x;

    for (int j = tid; j < KCL * DIMS; j += blockDim.x) sc[j] = cc[j];
    if (tid < KCL) { sfill[tid] = 0.0f; shist[tid] = 0; }
    __syncthreads();
    if (tid < KCL) {
        float s = 0.0f;
        const float* cp = sc + tid * DIMS;
        #pragma unroll
        for (int d = 0; d < DIMS; d++) s += cp[d] * cp[d];
        scn[tid] = s;
    }
    __syncthreads();

    const int i = blockIdx.x * CHUNK + tid;
    float xr[DIMS];
    {
        const float4* xp = (const float4*)(x + (size_t)i * DIMS);
        #pragma unroll
        for (int q = 0; q < 16; q++) {
            float4 v = xp[q];
            xr[4*q] = v.x; xr[4*q+1] = v.y; xr[4*q+2] = v.z; xr[4*q+3] = v.w;
        }
    }
    float xn = 0.0f;
    #pragma unroll
    for (int d = 0; d < DIMS; d++) xn += xr[d] * xr[d];

    // pass 1: wsum + argmin
    float wsum = 0.0f, best = BIGF;
    int bc = 0;
    for (int c = 0; c < KCL; c++) {
        const float4* cp = (const float4*)(sc + c * DIMS);
        float a0 = 0.f, a1 = 0.f, a2 = 0.f, a3 = 0.f;
        #pragma unroll
        for (int q = 0; q < 16; q++) {
            float4 v = cp[q];
            a0 += xr[4*q]   * v.x;
            a1 += xr[4*q+1] * v.y;
            a2 += xr[4*q+2] * v.z;
            a3 += xr[4*q+3] * v.w;
        }
        float dot = (a0 + a1) + (a2 + a3);
        float d2 = xn + scn[c] - 2.0f * dot;
        float dist = sqrtf(fmaxf(d2, 0.0f));
        if (dist < best) { best = dist; bc = c; }   // first-min like argmin
        wsum += __fdividef(1.0f, dist + EPSV);
    }
    const float inv = __fdividef(1.0f, wsum);
    const int lane = tid & 31;

    // pass 2: accumulate normalized weights per cluster
    for (int c = 0; c < KCL; c++) {
        const float4* cp = (const float4*)(sc + c * DIMS);
        float a0 = 0.f, a1 = 0.f, a2 = 0.f, a3 = 0.f;
        #pragma unroll
        for (int q = 0; q < 16; q++) {
            float4 v = cp[q];
            a0 += xr[4*q]   * v.x;
            a1 += xr[4*q+1] * v.y;
            a2 += xr[4*q+2] * v.z;
            a3 += xr[4*q+3] * v.w;
        }
        float dot = (a0 + a1) + (a2 + a3);
        float d2 = xn + scn[c] - 2.0f * dot;
        float w = __fdividef(1.0f, sqrtf(fmaxf(d2, 0.0f)) + EPSV) * inv;
        #pragma unroll
        for (int o = 16; o > 0; o >>= 1) w += __shfl_down_sync(0xffffffffu, w, o);
        if (lane == 0) atomicAdd(&sfill[c], w);
    }

    g_pred[i] = bc;
    atomicAdd(&shist[bc], 1);
    __syncthreads();
    if (tid < KCL) {
        atomicAdd(&g_fill[tid], sfill[tid]);
        g_histx[blockIdx.x * KCL + tid] = shist[tid];
    }
}

// ----------------------------------------------------------------------------
// K1b: per-block histogram for target predictions (input)
// ----------------------------------------------------------------------------
__global__ void k_hist_t(const int* __restrict__ predt) {
    __shared__ int sh[KCL];
    int tid = threadIdx.x;
    if (tid < KCL) sh[tid] = 0;
    __syncthreads();
    int c = predt[blockIdx.x * CHUNK + tid];
    atomicAdd(&sh[c], 1);
    __syncthreads();
    if (tid < KCL) g_histt[blockIdx.x * KCL + tid] = sh[tid];
}

// ----------------------------------------------------------------------------
// K2: exclusive scan of histograms (in place), cluster counts, m=min, P=pow2,
//     padded offsets, loss_fil.  Single block of 128 threads.
// ----------------------------------------------------------------------------
__global__ void k_scan(const float* __restrict__ ftgt) {
    const int c = threadIdx.x;  // 0..127
    int run = 0;
    for (int b = 0; b < NBLK; b++) {
        int v = g_histx[b * KCL + c];
        g_histx[b * KCL + c] = run;
        run += v;
    }
    const int cntx = run;
    run = 0;
    for (int b = 0; b < NBLK; b++) {
        int v = g_histt[b * KCL + c];
        g_histt[b * KCL + c] = run;
        run += v;
    }
    const int cntt = run;

    int m = min(cntx, cntt);
    g_m[c] = m;
    int P = 0;
    if (m > 0) { P = 1; while (P < m) P <<= 1; }
    g_P[c] = P;

    __shared__ int sp[KCL];
    sp[c] = P;
    __syncthreads();
    if (c == 0) {
        int acc = 0;
        for (int k = 0; k < KCL; k++) { g_off[k] = acc; acc += sp[k]; }
    }

    // loss_fil = mean_k (fill_k/N - ftgt_k)^2
    float diff = g_fill[c] * (1.0f / N_PTS) - ftgt[c];
    __shared__ float sd[KCL];
    sd[c] = diff * diff;
    __syncthreads();
    if (c == 0) {
        float s = 0.0f;
        for (int k = 0; k < KCL; k++) s += sd[k];
        g_loss[0] = (double)(s / KCL);
    }
}

// ----------------------------------------------------------------------------
// K3: stable rank within cluster (match_any over sequential warps) + gather
//     first m members' rows into column-major padded segments.
//     side == 0: x -> g_xg using g_pred/g_histx ; side == 1: target -> g_tg
// ----------------------------------------------------------------------------
__global__ void k_scatter(const float* __restrict__ src,
                          const int* __restrict__ predt, int side) {
    __shared__ int cnt[KCL];
    const int tid = threadIdx.x;
    if (tid < KCL) cnt[tid] = 0;
    __syncthreads();

    const int i = blockIdx.x * CHUNK + tid;
    const int c = side ? predt[i] : g_pred[i];
    const int myw = tid >> 5, lane = tid & 31;
    int lrank = 0;

    for (int w = 0; w < CHUNK / 32; w++) {
        if (myw == w) {
            unsigned peers = __match_any_sync(0xffffffffu, c);
            unsigned lower = peers & ((1u << lane) - 1u);
            int leader = __ffs(peers) - 1;
            int base = 0;
            if (lane == leader) base = atomicAdd(&cnt[c], __popc(peers));
            base = __shfl_sync(0xffffffffu, base, leader);
            lrank = base + __popc(lower);
        }
        __syncthreads();
    }

    const int* hist = side ? g_histt : g_histx;
    const int r = hist[blockIdx.x * KCL + c] + lrank;
    const int m = g_m[c];
    if (r < m) {
        const int P = g_P[c];
        float* dst = (side ? g_tg : g_xg) + (size_t)g_off[c] * DIMS + r;
        const float4* sp = (const float4*)(src + (size_t)i * DIMS);
        #pragma unroll
        for (int q = 0; q < 16; q++) {
            float4 v = sp[q];
            dst[(size_t)(4*q)     * P] = v.x;
            dst[(size_t)(4*q + 1) * P] = v.y;
            dst[(size_t)(4*q + 2) * P] = v.z;
            dst[(size_t)(4*q + 3) * P] = v.w;
        }
    }
}

// ----------------------------------------------------------------------------
// K4: per-(side, cluster, feature) bitonic sort in shared memory.
//     Block handles its segment iff lo < P <= hi.
// ----------------------------------------------------------------------------
__global__ void k_sort_smem(int lo, int hi) {
    const int s = blockIdx.x;
    float* buf = (s < KD) ? g_xg : g_tg;
    const int cd = (s < KD) ? s : s - KD;
    const int c = cd >> 6, d = cd & 63;
    const int m = g_m[c];
    if (m < 2) return;
    const int P = g_P[c];
    if (P <= lo || P > hi) return;

    extern __shared__ float sh[];
    float* seg = buf + (size_t)g_off[c] * DIMS + (size_t)d * P;
    const int T = blockDim.x, tid = threadIdx.x;

    for (int j = tid; j < P; j += T) sh[j] = (j < m) ? seg[j] : BIGF;
    __syncthreads();

    for (int k = 2; k <= P; k <<= 1) {
        for (int j = k >> 1; j > 0; j >>= 1) {
            for (int idx = tid; idx < P; idx += T) {
                int l = idx ^ j;
                if (l > idx) {
                    float a = sh[idx], b = sh[l];
                    bool up = ((idx & k) == 0);
                    if ((a > b) == up) { sh[idx] = b; sh[l] = a; }
                }
            }
            __syncthreads();
        }
    }
    for (int j = tid; j < m; j += T) seg[j] = sh[j];
}

// Fallback: sort directly in global memory for P > hi_smem (rare giant clusters)
__global__ void k_sort_global(int lo) {
    const int s = blockIdx.x;
    float* buf = (s < KD) ? g_xg : g_tg;
    const int cd = (s < KD) ? s : s - KD;
    const int c = cd >> 6, d = cd & 63;
    const int m = g_m[c];
    if (m < 2) return;
    const int P = g_P[c];
    if (P <= lo) return;

    float* seg = buf + (size_t)g_off[c] * DIMS + (size_t)d * P;
    const int T = blockDim.x, tid = threadIdx.x;
    for (int j = m + tid; j < P; j += T) seg[j] = BIGF;
    __syncthreads();

    for (int k = 2; k <= P; k <<= 1) {
        for (int j = k >> 1; j > 0; j >>= 1) {
            for (int idx = tid; idx < P; idx += T) {
                int l = idx ^ j;
                if (l > idx) {
                    float a = seg[idx], b = seg[l];
                    bool up = ((idx & k) == 0);
                    if ((a > b) == up) { seg[idx] = b; seg[l] = a; }
                }
            }
            __syncthreads();
        }
    }
}

// ----------------------------------------------------------------------------
// K5: Wasserstein sums: per (cluster, feature) sum |sorted_x - sorted_t| / (m*D)
// ----------------------------------------------------------------------------
__global__ void k_diff() {
    const int cd = blockIdx.x;
    const int c = cd >> 6, d = cd & 63;
    const int m = g_m[c];
    if (m < 1) return;
    const int P = g_P[c];
    const size_t base = (size_t)g_off[c] * DIMS + (size_t)d * P;

    float s = 0.0f;
    for (int j = threadIdx.x; j < m; j += blockDim.x)
        s += fabsf(g_xg[base + j] - g_tg[base + j]);

    __shared__ float red[256];
    red[threadIdx.x] = s;
    __syncthreads();
    for (int o = blockDim.x >> 1; o > 0; o >>= 1) {
        if (threadIdx.x < o) red[threadIdx.x] += red[threadIdx.x + o];
        __syncthreads();
    }
    if (threadIdx.x == 0)
        atomicAdd(&g_loss[1], (double)red[0] / ((double)m * DIMS));
}

// ----------------------------------------------------------------------------
// K6: finalize
// ----------------------------------------------------------------------------
__global__ void k_final(float* out) {
    out[0] = (float)(g_loss[0] + g_loss[1]);
}

// ----------------------------------------------------------------------------
// Launch
// ----------------------------------------------------------------------------
extern "C" void kernel_launch(void* const* d_in, const int* in_sizes, int n_in,
                              void* d_out, int out_size) {
    const float* x     = (const float*)d_in[0];
    const float* tgt   = (const float*)d_in[1];
    const float* cc    = (const float*)d_in[2];
    const int*   predt = (const int*)d_in[3];
    const float* ftgt  = (const float*)d_in[4];
    float* out = (float*)d_out;

    cudaFuncSetAttribute(k_sort_smem,
                         cudaFuncAttributeMaxDynamicSharedMemorySize, 131072);

    k_init<<<1, 128>>>();
    k_assign<<<NBLK, CHUNK>>>(x, cc);
    k_hist_t<<<NBLK, CHUNK>>>(predt);
    k_scan<<<1, KCL>>>(ftgt);
    k_scatter<<<NBLK, CHUNK>>>(x, predt, 0);
    k_scatter<<<NBLK, CHUNK>>>(tgt, predt, 1);
    // sort tiers: P in (1, 2048] with 8KB smem; (2048, 32768] with 128KB smem;
    // > 32768 in global memory (degenerate giant cluster).
    k_sort_smem<<<2 * KD, 256, 2048 * sizeof(float)>>>(1, 2048);
    k_sort_smem<<<2 * KD, 1024, 32768 * sizeof(float)>>>(2048, 32768);
    k_sort_global<<<2 * KD, 1024>>>(32768);
    k_diff<<<KD, 256>>>();
    k_final<<<1, 1>>>(out);
}